// round 5
// baseline (speedup 1.0000x reference)
#include <cuda_runtime.h>
#include <math.h>

#define Hh 2048
#define Wd 2048
#define MASKM 2047
#define Kk 16
#define Pp 15
#define TSTRIDE 144   // gather halo tile row stride

// scratch (static device globals — no allocation)
__device__ float g_rowsum[Hh * Wd];
__device__ float g_C;
__device__ int   g_dfast[Kk];   // smem-relative deltas (padded to 16, w=0)
__device__ float g_wfast[Kk];
__device__ int   g_ng;          // out-of-range shifts (never in practice)
__device__ int   g_gsy[Kk], g_gsx[Kk];
__device__ float g_gw[Kk];

// ---------------------------------------------------------------------------
// Kernel 1: horizontal sliding 15-sum (one block per row, 8 outputs/thread).
// Block 0 additionally does the prep work with FULLY PARALLEL dedupe
// (no serial chains, no local-memory arrays).
// ---------------------------------------------------------------------------
__global__ void __launch_bounds__(256)
k_rowsum_prep(const float* __restrict__ img,
              const float* __restrict__ patterns,
              const float* __restrict__ vectors) {
    int t = threadIdx.x;

    if (blockIdx.x == 0) {
        __shared__ float red[256];
        __shared__ int shy[Kk], shx[Kk];
        __shared__ int srare;

        if (t == 0) srare = 0;
        if (t < Kk) {
            float vy = __ldg(vectors + 2 * t);
            float vx = __ldg(vectors + 2 * t + 1);
            int ny = ((int)floorf(vy)) & MASKM; if (ny >= 1024) ny -= 2048;
            int nx = ((int)floorf(vx)) & MASKM; if (nx >= 1024) nx -= 2048;
            shy[t] = ny; shx[t] = nx;
        }
        // pattern sum: 3600 floats = 900 float4, 256 threads
        float s = 0.f;
        for (int i = t; i < 900; i += 256) {
            float4 f = __ldg((const float4*)patterns + i);
            s += f.x + f.y + f.z + f.w;
        }
        red[t] = s;
        __syncthreads();
        for (int off = 128; off > 0; off >>= 1) {
            if (t < off) red[t] += red[t + off];
            __syncthreads();
        }

        if (t < Kk) {
            int ny = shy[t], nx = shx[t];
            int cnt = 0, first = Kk;
            #pragma unroll
            for (int m = 0; m < Kk; m++) {
                bool eq = (shy[m] == ny) && (shx[m] == nx);
                cnt += eq ? 1 : 0;
                if (eq && m < first) first = m;
            }
            bool isfirst = (first == t);
            bool inr = (ny >= -8 && ny <= 8 && nx >= -8 && nx <= 8);
            if (isfirst && inr) {
                g_dfast[t] = -ny * TSTRIDE - nx;
                g_wfast[t] = (float)cnt;
            } else {
                g_dfast[t] = 0;
                g_wfast[t] = 0.f;
            }
            if (isfirst && !inr) {
                int idx = atomicAdd(&srare, 1);
                g_gsy[idx] = ny; g_gsx[idx] = nx; g_gw[idx] = (float)cnt;
            }
        }
        __syncthreads();
        if (t == 0) {
            g_ng = srare;
            g_C = ((float)Kk - red[0] / (float)(Pp * Pp)) / (float)(Kk - 1);
        }
    }

    // ---- rowsum for this row ----
    int i = blockIdx.x;
    int j0 = t * 8;
    const float* row = img + (size_t)i * Wd;

    float v[24];  // v[x] = img[i][j0-16+x]
    if (j0 >= 16) {
        const float4* p = (const float4*)(row + j0 - 16);
        #pragma unroll
        for (int q = 0; q < 6; q++) {
            float4 f = __ldg(p + q);
            v[4 * q + 0] = f.x; v[4 * q + 1] = f.y;
            v[4 * q + 2] = f.z; v[4 * q + 3] = f.w;
        }
    } else {
        #pragma unroll
        for (int x = 0; x < 24; x++) {
            int c = j0 - 16 + x;
            v[x] = (c >= 0) ? __ldg(row + c) : 0.f;
        }
    }

    float s = 0.f;
    #pragma unroll
    for (int x = 1; x <= 15; x++) s += v[x];
    float o[8];
    o[0] = s;
    #pragma unroll
    for (int c = 1; c < 8; c++) { s += v[15 + c] - v[c]; o[c] = s; }

    float4* outp = (float4*)(g_rowsum + (size_t)i * Wd + j0);
    outp[0] = make_float4(o[0], o[1], o[2], o[3]);
    outp[1] = make_float4(o[4], o[5], o[6], o[7]);
}

// ---------------------------------------------------------------------------
// Kernel 2: fused vertical 15-sum + weighted shifted gather.
// Per block (64 rows x 128 cols of out): build the 80x144 win halo tile in
// SMEM via column-parallel sliding sums over g_rowsum (wrap-safe segments),
// then branch-free fully-unrolled 16-entry gather (R4-style).
// win[r][c] = sum_{t=1..15} RZ(r-t, c),  RZ zero for row<0.
// grid = (16, 32), 256 threads.
// ---------------------------------------------------------------------------
__global__ void __launch_bounds__(256) k_wingather(float* __restrict__ out) {
    __shared__ float tile[80 * TSTRIDE];
    __shared__ int   sd[Kk];
    __shared__ float sw[Kk];
    __shared__ int   sng;
    __shared__ float sC;

    int t = threadIdx.x;
    int j0 = blockIdx.x * 128;
    int i0 = blockIdx.y * 64;

    if (t < Kk) { sd[t] = g_dfast[t]; sw[t] = g_wfast[t]; }
    if (t == 0) { sng = g_ng; sC = g_C; }

    // ---- phase 1: compute win tile rows v=0..79 (global row (i0-8+v)&M),
    //      cols c=0..143 (global col (j0-8+c)&M). 288 tasks = 144 cols x 2
    //      row-chunks of 40.
    int vw = (8 - i0) & MASKM;   // v where the wrapped row index jumps; >=80: none
    for (int task = t; task < 288; task += 256) {
        int h = (task >= 144) ? 1 : 0;
        int c = task - h * 144;
        int gc = (j0 - 8 + c) & MASKM;
        const float* colp = g_rowsum + gc;
        int v0 = h * 40, v1 = v0 + 40;

        int sa = v0;
        while (sa < v1) {
            int sb = (vw > sa && vw < v1) ? vw : v1;
            int A = (i0 - 8 + sa) & MASKM;   // global row of win at v=sa
            float s = 0.f;
            #pragma unroll
            for (int q = 1; q <= 15; q++) {
                int r = A - q;
                if (r >= 0) s += __ldg(colp + (size_t)r * Wd);
            }
            for (int v = sa; v < sb; v++) {
                tile[v * TSTRIDE + c] = s;
                if (v + 1 < sb) {
                    int Av = A + (v - sa);
                    float addv = __ldg(colp + (size_t)Av * Wd);
                    int rm = Av - 15;
                    float subv = (rm >= 0) ? __ldg(colp + (size_t)rm * Wd) : 0.f;
                    s += addv - subv;
                }
            }
            sa = sb;
        }
    }
    __syncthreads();

    // ---- phase 2: gather ----
    int tx = t & 127;
    int R0 = (t >> 7) * 32;   // 0 or 32
    const float* base = tile + (R0 + 8) * TSTRIDE + tx + 8;

    float acc[32];
    #pragma unroll
    for (int rr = 0; rr < 32; rr++) acc[rr] = 0.f;

    #pragma unroll
    for (int m = 0; m < Kk; m++) {
        float w = sw[m];
        const float* p = base + sd[m];
        #pragma unroll
        for (int rr = 0; rr < 32; rr++)
            acc[rr] += w * p[rr * TSTRIDE];
    }

    int ng = sng;
    if (ng > 0) {   // out-of-range shifts: compute win from rowsum directly
        for (int m = 0; m < ng; m++) {
            int sy = g_gsy[m], sx = g_gsx[m];
            float w = g_gw[m];
            int gc = (j0 + tx - sx) & MASKM;
            #pragma unroll 1
            for (int rr = 0; rr < 32; rr++) {
                int gr = (i0 + R0 + rr - sy) & MASKM;
                float vsum = 0.f;
                #pragma unroll
                for (int q = 1; q <= 15; q++) {
                    int r = gr - q;
                    if (r >= 0) vsum += __ldg(g_rowsum + (size_t)r * Wd + gc);
                }
                acc[rr] += w * vsum;
            }
        }
    }

    const float scale = 1.0f / 3375.0f;
    float cbias = sC;
    float* op = out + (size_t)(i0 + R0) * Wd + j0 + tx;
    #pragma unroll
    for (int rr = 0; rr < 32; rr++)
        op[(size_t)rr * Wd] = cbias + scale * acc[rr];
}

// ---------------------------------------------------------------------------
extern "C" void kernel_launch(void* const* d_in, const int* in_sizes, int n_in,
                              void* d_out, int out_size) {
    const float* x        = (const float*)d_in[0];  // (1,1,2048,2048)
    const float* patterns = (const float*)d_in[1];  // (16,15,15)
    const float* vectors  = (const float*)d_in[2];  // (16,2)
    float* out = (float*)d_out;                     // (2048,2048)

    k_rowsum_prep<<<Hh, 256>>>(x, patterns, vectors);
    k_wingather<<<dim3(16, 32), 256>>>(out);
}

// round 6
// speedup vs baseline: 1.3149x; 1.3149x over previous
#include <cuda_runtime.h>
#include <math.h>

#define Hh 2048
#define Wd 2048
#define MASKM 2047
#define Kk 16
#define Pp 15
#define TSTRIDE 144   // gather halo tile row stride

// scratch (static device globals — no allocation)
__device__ float g_win[Hh * Wd];
__device__ float g_C;
__device__ int   g_dfast[Kk];   // smem-relative deltas (padded to 16, w=0)
__device__ float g_wfast[Kk];
__device__ int   g_ng;          // out-of-range shifts (never in practice)
__device__ int   g_gsy[Kk], g_gsx[Kk];
__device__ float g_gw[Kk];

// ---------------------------------------------------------------------------
// Kernel 1: fused separable 15x15 box-sum (zero-padded above/left).
// win[i][j] = sum_{a=i-15..i-1, b=j-15..j-1} img[a][b]
// Tile: 128 rows x 64 cols per block; rowsum staged in SMEM (143 x 64,
// stride 65). grid = (32, 16), 256 threads.
// Block (0,0) additionally does ALL prep work with fully-parallel dedupe.
// ---------------------------------------------------------------------------
__global__ void __launch_bounds__(256)
k_box(const float* __restrict__ img,
      const float* __restrict__ patterns,
      const float* __restrict__ vectors) {
    __shared__ float rs[143 * 65];

    int t = threadIdx.x;
    int j0 = blockIdx.x * 64;
    int i0 = blockIdx.y * 128;

    // ---- prep (block (0,0) only): pattern sum, parallel dedupe ----
    if (blockIdx.x == 0 && blockIdx.y == 0) {
        __shared__ float red[256];
        __shared__ int shy[Kk], shx[Kk];
        __shared__ int srare;

        if (t == 0) srare = 0;
        if (t < Kk) {
            float vy = __ldg(vectors + 2 * t);
            float vx = __ldg(vectors + 2 * t + 1);
            int ny = ((int)floorf(vy)) & MASKM; if (ny >= 1024) ny -= 2048;
            int nx = ((int)floorf(vx)) & MASKM; if (nx >= 1024) nx -= 2048;
            shy[t] = ny; shx[t] = nx;
        }
        float s = 0.f;
        for (int i = t; i < 900; i += 256) {   // 3600 floats = 900 float4
            float4 f = __ldg((const float4*)patterns + i);
            s += f.x + f.y + f.z + f.w;
        }
        red[t] = s;
        __syncthreads();
        for (int off = 128; off > 0; off >>= 1) {
            if (t < off) red[t] += red[t + off];
            __syncthreads();
        }
        if (t < Kk) {
            int ny = shy[t], nx = shx[t];
            int cnt = 0, first = Kk;
            #pragma unroll
            for (int m = 0; m < Kk; m++) {
                bool eq = (shy[m] == ny) && (shx[m] == nx);
                cnt += eq ? 1 : 0;
                if (eq && m < first) first = m;
            }
            bool isfirst = (first == t);
            bool inr = (ny >= -8 && ny <= 8 && nx >= -8 && nx <= 8);
            if (isfirst && inr) {
                g_dfast[t] = -ny * TSTRIDE - nx;
                g_wfast[t] = (float)cnt;
            } else {
                g_dfast[t] = 0;
                g_wfast[t] = 0.f;
            }
            if (isfirst && !inr) {
                int idx = atomicAdd(&srare, 1);
                g_gsy[idx] = ny; g_gsx[idx] = nx; g_gw[idx] = (float)cnt;
            }
        }
        __syncthreads();
        if (t == 0) {
            g_ng = srare;
            g_C = ((float)Kk - red[0] / (float)(Pp * Pp)) / (float)(Kk - 1);
        }
        __syncthreads();
    }

    // ---- phase 1: horizontal sliding sum into rs ----
    for (int tt = t; tt < 143 * 8; tt += 256) {
        int r   = tt >> 3;
        int seg = tt & 7;
        int arow = i0 - 15 + r;
        int jb = j0 + seg * 8;
        float o[8];
        if (arow < 0) {
            #pragma unroll
            for (int c = 0; c < 8; c++) o[c] = 0.f;
        } else {
            const float* row = img + (size_t)arow * Wd;
            float v[24];
            if (jb >= 16) {
                const float4* p = (const float4*)(row + jb - 16);
                #pragma unroll
                for (int q = 0; q < 6; q++) {
                    float4 f = __ldg(p + q);
                    v[4 * q + 0] = f.x; v[4 * q + 1] = f.y;
                    v[4 * q + 2] = f.z; v[4 * q + 3] = f.w;
                }
            } else {
                #pragma unroll
                for (int x = 0; x < 24; x++) {
                    int c = jb - 16 + x;
                    v[x] = (c >= 0) ? __ldg(row + c) : 0.f;
                }
            }
            float s = 0.f;
            #pragma unroll
            for (int x = 1; x <= 15; x++) s += v[x];
            o[0] = s;
            #pragma unroll
            for (int c = 1; c < 8; c++) { s += v[15 + c] - v[c]; o[c] = s; }
        }
        float* dst = rs + r * 65 + seg * 8;
        #pragma unroll
        for (int c = 0; c < 8; c++) dst[c] = o[c];
    }
    __syncthreads();

    // ---- phase 2: vertical sliding sum -> win (SMEM chains, fast) ----
    int col = t & 63;
    int R0  = (t >> 6) * 32;
    const float* cp = rs + col;
    float s = 0.f;
    #pragma unroll
    for (int r = 0; r < 15; r++) s += cp[(R0 + r) * 65];
    float* outp = g_win + (size_t)(i0 + R0) * Wd + j0 + col;
    #pragma unroll
    for (int rr = 0; rr < 32; rr++) {
        outp[(size_t)rr * Wd] = s;
        if (rr < 31)
            s += cp[(R0 + rr + 15) * 65] - cp[(R0 + rr) * 65];
    }
}

// ---------------------------------------------------------------------------
// Kernel 2: out[i,j] = C + (1/3375)*sum_m w_m * win[(i-sy)&M][(j-sx)&M]
// 64x128 tile/block; 80x144 halo in SMEM (46KB). Branch-free fully-unrolled
// 16-entry fast loop (zero-weight padding); rare uniform global fallback.
// grid = (16, 32), 256 threads; thread = 1 col x 32 rows.
// ---------------------------------------------------------------------------
__global__ void __launch_bounds__(256) k_gather(float* __restrict__ out) {
    __shared__ float tile[80 * TSTRIDE];
    __shared__ int   sd[Kk];
    __shared__ float sw[Kk];
    __shared__ int   sng;
    __shared__ float sC;

    int t = threadIdx.x;
    int j0 = blockIdx.x * 128;
    int i0 = blockIdx.y * 64;

    if (t < Kk) { sd[t] = g_dfast[t]; sw[t] = g_wfast[t]; }
    if (t == 0) { sng = g_ng; sC = g_C; }

    // stage 80 x 144 halo via float4 (j0-8 ≡ 0 mod 4; wrap never splits)
    for (int idx = t; idx < 80 * 36; idx += 256) {
        int u  = idx / 36;
        int vq = idx - u * 36;
        int gr = (i0 - 8 + u) & MASKM;
        int gc = (j0 - 8 + 4 * vq) & MASKM;
        float4 f = __ldg((const float4*)(g_win + (size_t)gr * Wd + gc));
        *(float4*)&tile[u * TSTRIDE + 4 * vq] = f;
    }
    __syncthreads();

    int tx = t & 127;
    int R0 = (t >> 7) * 32;   // 0 or 32
    const float* base = tile + (R0 + 8) * TSTRIDE + tx + 8;

    float acc[32];
    #pragma unroll
    for (int rr = 0; rr < 32; rr++) acc[rr] = 0.f;

    #pragma unroll
    for (int m = 0; m < Kk; m++) {
        float w = sw[m];
        const float* p = base + sd[m];
        #pragma unroll
        for (int rr = 0; rr < 32; rr++)
            acc[rr] += w * p[rr * TSTRIDE];
    }

    int ng = sng;
    if (ng > 0) {  // uniform, essentially never taken
        for (int m = 0; m < ng; m++) {
            int sy = g_gsy[m], sx = g_gsx[m];
            float w = g_gw[m];
            int gc = (j0 + tx - sx) & MASKM;
            #pragma unroll 1
            for (int rr = 0; rr < 32; rr++) {
                int gr = (i0 + R0 + rr - sy) & MASKM;
                acc[rr] += w * __ldg(g_win + (size_t)gr * Wd + gc);
            }
        }
    }

    const float scale = 1.0f / 3375.0f;
    float c = sC;
    float* op = out + (size_t)(i0 + R0) * Wd + j0 + tx;
    #pragma unroll
    for (int rr = 0; rr < 32; rr++)
        op[(size_t)rr * Wd] = c + scale * acc[rr];
}

// ---------------------------------------------------------------------------
extern "C" void kernel_launch(void* const* d_in, const int* in_sizes, int n_in,
                              void* d_out, int out_size) {
    const float* x        = (const float*)d_in[0];  // (1,1,2048,2048)
    const float* patterns = (const float*)d_in[1];  // (16,15,15)
    const float* vectors  = (const float*)d_in[2];  // (16,2)
    float* out = (float*)d_out;                     // (2048,2048)

    k_box<<<dim3(32, 16), 256>>>(x, patterns, vectors);
    k_gather<<<dim3(16, 32), 256>>>(out);
}

// round 7
// speedup vs baseline: 1.4057x; 1.0691x over previous
#include <cuda_runtime.h>
#include <math.h>

#define Hh 2048
#define Wd 2048
#define MASKM 2047
#define Kk 16
#define Pp 15
#define TSTRIDE 144   // gather halo tile row stride

// scratch (static device globals — no allocation)
__device__ float g_win[Hh * Wd];
__device__ float g_C;
__device__ int   g_dfast[Kk];   // smem-relative deltas (padded to 16, w=0)
__device__ float g_wfast[Kk];   // weights premultiplied by 1/3375
__device__ int   g_ng;          // out-of-range shifts (never in practice)
__device__ int   g_gsy[Kk], g_gsx[Kk];
__device__ float g_gw[Kk];      // premultiplied by 1/3375

// ---------------------------------------------------------------------------
// Kernel 1: fused separable 15x15 box-sum (zero-padded above/left).
// win[i][j] = sum_{a=i-15..i-1, b=j-15..j-1} img[a][b]
// Tile: 128 rows x 64 cols per block; rowsum staged in SMEM (143 x 64,
// stride 65). grid = (32, 16), 256 threads.
// Block (0,0) additionally does ALL prep work with fully-parallel dedupe.
// ---------------------------------------------------------------------------
__global__ void __launch_bounds__(256)
k_box(const float* __restrict__ img,
      const float* __restrict__ patterns,
      const float* __restrict__ vectors) {
    __shared__ float rs[143 * 65];

    int t = threadIdx.x;
    int j0 = blockIdx.x * 64;
    int i0 = blockIdx.y * 128;

    // ---- prep (block (0,0) only) ----
    if (blockIdx.x == 0 && blockIdx.y == 0) {
        __shared__ float red[256];
        __shared__ int shy[Kk], shx[Kk];
        __shared__ int srare;
        const float scale = 1.0f / 3375.0f;

        if (t == 0) srare = 0;
        if (t < Kk) {
            float vy = __ldg(vectors + 2 * t);
            float vx = __ldg(vectors + 2 * t + 1);
            int ny = ((int)floorf(vy)) & MASKM; if (ny >= 1024) ny -= 2048;
            int nx = ((int)floorf(vx)) & MASKM; if (nx >= 1024) nx -= 2048;
            shy[t] = ny; shx[t] = nx;
        }
        float s = 0.f;
        for (int i = t; i < 900; i += 256) {   // 3600 floats = 900 float4
            float4 f = __ldg((const float4*)patterns + i);
            s += f.x + f.y + f.z + f.w;
        }
        red[t] = s;
        __syncthreads();
        for (int off = 128; off > 0; off >>= 1) {
            if (t < off) red[t] += red[t + off];
            __syncthreads();
        }
        if (t < Kk) {
            int ny = shy[t], nx = shx[t];
            int cnt = 0, first = Kk;
            #pragma unroll
            for (int m = 0; m < Kk; m++) {
                bool eq = (shy[m] == ny) && (shx[m] == nx);
                cnt += eq ? 1 : 0;
                if (eq && m < first) first = m;
            }
            bool isfirst = (first == t);
            bool inr = (ny >= -8 && ny <= 8 && nx >= -8 && nx <= 8);
            if (isfirst && inr) {
                g_dfast[t] = -ny * TSTRIDE - nx;
                g_wfast[t] = (float)cnt * scale;
            } else {
                g_dfast[t] = 0;
                g_wfast[t] = 0.f;
            }
            if (isfirst && !inr) {
                int idx = atomicAdd(&srare, 1);
                g_gsy[idx] = ny; g_gsx[idx] = nx;
                g_gw[idx] = (float)cnt * scale;
            }
        }
        __syncthreads();
        if (t == 0) {
            g_ng = srare;
            g_C = ((float)Kk - red[0] / (float)(Pp * Pp)) / (float)(Kk - 1);
        }
        __syncthreads();
    }

    // ---- phase 1: horizontal sliding sum into rs ----
    for (int tt = t; tt < 143 * 8; tt += 256) {
        int r   = tt >> 3;
        int seg = tt & 7;
        int arow = i0 - 15 + r;
        int jb = j0 + seg * 8;
        float o[8];
        if (arow < 0) {
            #pragma unroll
            for (int c = 0; c < 8; c++) o[c] = 0.f;
        } else {
            const float* row = img + (size_t)arow * Wd;
            float v[24];
            if (jb >= 16) {
                const float4* p = (const float4*)(row + jb - 16);
                #pragma unroll
                for (int q = 0; q < 6; q++) {
                    float4 f = __ldg(p + q);
                    v[4 * q + 0] = f.x; v[4 * q + 1] = f.y;
                    v[4 * q + 2] = f.z; v[4 * q + 3] = f.w;
                }
            } else {
                #pragma unroll
                for (int x = 0; x < 24; x++) {
                    int c = jb - 16 + x;
                    v[x] = (c >= 0) ? __ldg(row + c) : 0.f;
                }
            }
            float s = 0.f;
            #pragma unroll
            for (int x = 1; x <= 15; x++) s += v[x];
            o[0] = s;
            #pragma unroll
            for (int c = 1; c < 8; c++) { s += v[15 + c] - v[c]; o[c] = s; }
        }
        float* dst = rs + r * 65 + seg * 8;
        #pragma unroll
        for (int c = 0; c < 8; c++) dst[c] = o[c];
    }
    __syncthreads();

    // ---- phase 2: vertical sliding sum -> win ----
    int col = t & 63;
    int R0  = (t >> 6) * 32;
    const float* cp = rs + col;
    float s = 0.f;
    #pragma unroll
    for (int r = 0; r < 15; r++) s += cp[(R0 + r) * 65];
    float* outp = g_win + (size_t)(i0 + R0) * Wd + j0 + col;
    #pragma unroll
    for (int rr = 0; rr < 32; rr++) {
        outp[(size_t)rr * Wd] = s;
        if (rr < 31)
            s += cp[(R0 + rr + 15) * 65] - cp[(R0 + rr) * 65];
    }
}

// ---------------------------------------------------------------------------
// Kernel 2: out[i,j] = C + sum_m w'_m * win[(i-sy)&M][(j-sx)&M]
// (weights premultiplied by 1/3375)
// 32x128 tile/block; 48x144 halo in SMEM (27.6KB -> ~7 blocks/SM).
// Branch-free fully-unrolled 16-entry fast loop; rare uniform fallback.
// grid = (16, 64), 256 threads; thread = 1 col x 16 rows.
// ---------------------------------------------------------------------------
__global__ void __launch_bounds__(256) k_gather(float* __restrict__ out) {
    __shared__ float tile[48 * TSTRIDE];
    __shared__ int   sd[Kk];
    __shared__ float sw[Kk];
    __shared__ int   sng;
    __shared__ float sC;

    int t = threadIdx.x;
    int j0 = blockIdx.x * 128;
    int i0 = blockIdx.y * 32;

    if (t < Kk) { sd[t] = g_dfast[t]; sw[t] = g_wfast[t]; }
    if (t == 0) { sng = g_ng; sC = g_C; }

    // stage 48 x 144 halo via float4 (j0-8 ≡ 0 mod 4; wrap never splits)
    for (int idx = t; idx < 48 * 36; idx += 256) {
        int u  = idx / 36;
        int vq = idx - u * 36;
        int gr = (i0 - 8 + u) & MASKM;
        int gc = (j0 - 8 + 4 * vq) & MASKM;
        float4 f = __ldg((const float4*)(g_win + (size_t)gr * Wd + gc));
        *(float4*)&tile[u * TSTRIDE + 4 * vq] = f;
    }
    __syncthreads();

    int tx = t & 127;
    int R0 = (t >> 7) * 16;   // 0 or 16
    const float* base = tile + (R0 + 8) * TSTRIDE + tx + 8;

    float acc[16];
    #pragma unroll
    for (int rr = 0; rr < 16; rr++) acc[rr] = 0.f;

    #pragma unroll
    for (int m = 0; m < Kk; m++) {
        float w = sw[m];
        const float* p = base + sd[m];
        #pragma unroll
        for (int rr = 0; rr < 16; rr++)
            acc[rr] += w * p[rr * TSTRIDE];
    }

    int ng = sng;
    if (ng > 0) {  // uniform, essentially never taken
        for (int m = 0; m < ng; m++) {
            int sy = g_gsy[m], sx = g_gsx[m];
            float w = g_gw[m];
            int gc = (j0 + tx - sx) & MASKM;
            #pragma unroll 1
            for (int rr = 0; rr < 16; rr++) {
                int gr = (i0 + R0 + rr - sy) & MASKM;
                acc[rr] += w * __ldg(g_win + (size_t)gr * Wd + gc);
            }
        }
    }

    float c = sC;
    float* op = out + (size_t)(i0 + R0) * Wd + j0 + tx;
    #pragma unroll
    for (int rr = 0; rr < 16; rr++)
        op[(size_t)rr * Wd] = c + acc[rr];
}

// ---------------------------------------------------------------------------
extern "C" void kernel_launch(void* const* d_in, const int* in_sizes, int n_in,
                              void* d_out, int out_size) {
    const float* x        = (const float*)d_in[0];  // (1,1,2048,2048)
    const float* patterns = (const float*)d_in[1];  // (16,15,15)
    const float* vectors  = (const float*)d_in[2];  // (16,2)
    float* out = (float*)d_out;                     // (2048,2048)

    k_box<<<dim3(32, 16), 256>>>(x, patterns, vectors);
    k_gather<<<dim3(16, 64), 256>>>(out);
}